// round 2
// baseline (speedup 1.0000x reference)
#include <cuda_runtime.h>

// Problem constants (fixed shapes for this problem instance)
#define NPTS 65536   // N input points
#define MPTS 65536   // M support points
#define CIN  64      // input channels
#define KNB  16      // neighbors per support point
#define HID  64      // MLP hidden
#define OUTC 128     // output channels
#define CH   67      // CIN + 3

#define TM   16            // support points per block
#define COLS 256           // TM * KNB columns per tile
#define SH_STRIDE  67      // odd stride -> conflict-free LDS in GEMM1
#define SH1_STRIDE 65      // odd stride -> conflict-free LDS in GEMM2

// Scratch (allocation-free rule: __device__ globals)
__device__ float g_xT[(size_t)NPTS * CIN];   // x transposed: [N][64]
__device__ float g_W1t[CH * HID];            // W1 transposed: [67][64]
__device__ float g_W2t[HID * OUTC];          // W2 transposed: [64][128]
__device__ int   g_idx_is64;                 // 1 if indices buffer is int64

// ---------------------------------------------------------------------------
// Detect index dtype: for int64 (values < 2^31, non-negative) every odd
// 32-bit word is zero. For real int32 index data that's ~impossible.
// ---------------------------------------------------------------------------
__global__ void detect_idx_kernel(const unsigned int* __restrict__ idx32)
{
    if (threadIdx.x == 0 && blockIdx.x == 0) {
        unsigned int orv = 0;
#pragma unroll 4
        for (int i = 0; i < 256; i++) orv |= idx32[2 * i + 1];
        g_idx_is64 = (orv == 0u) ? 1 : 0;
    }
}

// ---------------------------------------------------------------------------
// Prep: transpose x (channel-major -> point-major) and weights
// ---------------------------------------------------------------------------
__global__ void prep_kernel(const float* __restrict__ x,
                            const float* __restrict__ W1,
                            const float* __restrict__ W2)
{
    int tid = blockIdx.x * blockDim.x + threadIdx.x;

    if (tid < NPTS) {
        int n = tid;
#pragma unroll
        for (int c4 = 0; c4 < CIN / 4; c4++) {
            float4 v;
            v.x = x[(c4 * 4 + 0) * NPTS + n];
            v.y = x[(c4 * 4 + 1) * NPTS + n];
            v.z = x[(c4 * 4 + 2) * NPTS + n];
            v.w = x[(c4 * 4 + 3) * NPTS + n];
            *(float4*)&g_xT[(size_t)n * CIN + c4 * 4] = v;
        }
    }
    if (tid < CH * HID) {
        int c = tid / HID, o = tid % HID;
        g_W1t[c * HID + o] = W1[o * CH + c];
    }
    if (tid < HID * OUTC) {
        int c = tid / OUTC, o = tid % OUTC;
        g_W2t[c * OUTC + o] = W2[o * HID + c];
    }
}

// ---------------------------------------------------------------------------
// Fused: gather -> MLP1(relu) -> MLP2 -> max-pool over K
// Block: 256 threads = 16(ty: output-row groups) x 16(tx: support point).
// Columns k-major: col = k*16 + m_local, so thread tx owns all 16 neighbors
// of support point (m_base + tx) -> in-register max-pool.
// ---------------------------------------------------------------------------
extern __shared__ float smem[];

__global__ __launch_bounds__(256, 1)
void pointnet_kernel(const float* __restrict__ pos,
                     const float* __restrict__ sup,
                     const float* __restrict__ b1,
                     const float* __restrict__ b2,
                     const void* __restrict__ indices,
                     float* __restrict__ out)
{
    float* sh_h  = smem;                        // [COLS][SH_STRIDE]
    float* sh_h1 = smem + COLS * SH_STRIDE;     // [COLS][SH1_STRIDE]

    const int tid = threadIdx.x;
    const int tx  = tid & 15;
    const int ty  = tid >> 4;
    const int m_base = blockIdx.x * TM;

    // ---- Gather: one column per thread ----
    {
        int col = tid;               // col = k*16 + m_l
        int m_l = col & 15;
        int k   = col >> 4;
        long long lin = ((long long)(m_base + m_l)) * KNB + k;
        long long idxv;
        if (g_idx_is64) idxv = ((const long long*)indices)[lin];
        else            idxv = (long long)(((const int*)indices)[lin]);
        int ii = ((int)idxv) & (NPTS - 1);   // safety mask (NPTS is pow2)

        const float4* xr = (const float4*)&g_xT[(size_t)ii * CIN];
        float* dst = &sh_h[col * SH_STRIDE];
#pragma unroll
        for (int c4 = 0; c4 < CIN / 4; c4++) {
            float4 v = xr[c4];
            dst[c4 * 4 + 0] = v.x;
            dst[c4 * 4 + 1] = v.y;
            dst[c4 * 4 + 2] = v.z;
            dst[c4 * 4 + 3] = v.w;
        }
#pragma unroll
        for (int d = 0; d < 3; d++)
            dst[CIN + d] = pos[d * NPTS + ii] - sup[d * MPTS + m_base + m_l];
    }
    __syncthreads();

    // ---- GEMM1: h1[o][col] = relu(W1 . h + b1), o in [ty*4, ty*4+4) ----
    {
        float acc[4][16];
        float b1v[4];
#pragma unroll
        for (int r = 0; r < 4; r++) b1v[r] = __ldg(&b1[ty * 4 + r]);
#pragma unroll
        for (int j = 0; j < 16; j++) {
#pragma unroll
            for (int r = 0; r < 4; r++) acc[r][j] = b1v[r];
        }
#pragma unroll 1
        for (int c = 0; c < CH; c++) {
            float4 w = *(const float4*)&g_W1t[c * HID + ty * 4];
#pragma unroll
            for (int j = 0; j < 16; j++) {
                float hv = sh_h[(j * 16 + tx) * SH_STRIDE + c];
                acc[0][j] += w.x * hv;
                acc[1][j] += w.y * hv;
                acc[2][j] += w.z * hv;
                acc[3][j] += w.w * hv;
            }
        }
#pragma unroll
        for (int j = 0; j < 16; j++) {
            int col = j * 16 + tx;
#pragma unroll
            for (int r = 0; r < 4; r++)
                sh_h1[col * SH1_STRIDE + ty * 4 + r] = fmaxf(acc[r][j], 0.0f);
        }
    }
    __syncthreads();

    // ---- GEMM2 + max-pool: out[o][m] = max_k (W2 . h1 + b2) ----
#pragma unroll 1
    for (int rh = 0; rh < 2; rh++) {
        float acc[4][16];
        float b2v[4];
#pragma unroll
        for (int r = 0; r < 4; r++) b2v[r] = __ldg(&b2[rh * 64 + ty * 4 + r]);
#pragma unroll
        for (int j = 0; j < 16; j++) {
#pragma unroll
            for (int r = 0; r < 4; r++) acc[r][j] = b2v[r];
        }
#pragma unroll 1
        for (int c = 0; c < HID; c++) {
            float4 w = *(const float4*)&g_W2t[c * OUTC + rh * 64 + ty * 4];
#pragma unroll
            for (int j = 0; j < 16; j++) {
                float hv = sh_h1[(j * 16 + tx) * SH1_STRIDE + c];
                acc[0][j] += w.x * hv;
                acc[1][j] += w.y * hv;
                acc[2][j] += w.z * hv;
                acc[3][j] += w.w * hv;
            }
        }
#pragma unroll
        for (int r = 0; r < 4; r++) {
            float mx = acc[r][0];
#pragma unroll
            for (int j = 1; j < 16; j++) mx = fmaxf(mx, acc[r][j]);
            int o = rh * 64 + ty * 4 + r;
            out[(size_t)o * MPTS + m_base + tx] = mx;
        }
    }
}

// ---------------------------------------------------------------------------
extern "C" void kernel_launch(void* const* d_in, const int* in_sizes, int n_in,
                              void* d_out, int out_size)
{
    // Size-based input identification (robust to ordering changes).
    const float *x = 0, *pos = 0, *sup = 0, *W1 = 0, *b1 = 0, *W2 = 0, *b2 = 0;
    const void* idx = 0;
    for (int i = 0; i < n_in; i++) {
        switch (in_sizes[i]) {
            case 4194304: x  = (const float*)d_in[i]; break;          // 64*65536
            case 196608:  if (!pos) pos = (const float*)d_in[i];      // 3*65536
                          else      sup = (const float*)d_in[i]; break;
            case 4288:    W1 = (const float*)d_in[i]; break;          // 64*67
            case 64:      b1 = (const float*)d_in[i]; break;
            case 8192:    W2 = (const float*)d_in[i]; break;          // 128*64
            case 128:     b2 = (const float*)d_in[i]; break;
            case 1048576: idx = d_in[i]; break;                       // 65536*16
            default: break;
        }
    }
    float* out = (float*)d_out;

    detect_idx_kernel<<<1, 32>>>((const unsigned int*)idx);
    prep_kernel<<<(NPTS + 255) / 256, 256>>>(x, W1, W2);

    size_t smem_bytes = (size_t)(COLS * SH_STRIDE + COLS * SH1_STRIDE) * sizeof(float);
    cudaFuncSetAttribute(pointnet_kernel,
                         cudaFuncAttributeMaxDynamicSharedMemorySize,
                         (int)smem_bytes);
    pointnet_kernel<<<MPTS / TM, 256, smem_bytes>>>(pos, sup, b1, b2, idx, out);
}

// round 3
// speedup vs baseline: 1.8039x; 1.8039x over previous
#include <cuda_runtime.h>

// Problem constants
#define NPTS 65536
#define MPTS 65536
#define CIN  64
#define KNB  16
#define HID  64
#define OUTC 128
#define CH   67      // CIN + 3

// Tile: 8 support points x 16 neighbors = 128 columns per CTA
#define TM    8
#define COLS  128

// Scratch (__device__ globals: allocation-free rule)
__device__ float g_xT[(size_t)NPTS * CIN];   // x transposed: [N][64]
__device__ float g_W1t[CH * HID];            // W1 transposed: [67][64]
__device__ float g_W2t[HID * OUTC];          // W2 transposed: [64][128]
__device__ int   g_idx_is64;

// ---------------------------------------------------------------------------
// f32x2 packed helpers (FFMA2: full-rate fp32 pipe; ptxas never auto-emits)
// ---------------------------------------------------------------------------
typedef unsigned long long ull;

__device__ __forceinline__ ull fma2(ull a, ull b, ull c) {
    ull d;
    asm("fma.rn.f32x2 %0, %1, %2, %3;" : "=l"(d) : "l"(a), "l"(b), "l"(c));
    return d;
}
__device__ __forceinline__ ull dup2(float x) {
    ull d; unsigned int u = __float_as_uint(x);
    asm("mov.b64 %0, {%1, %1};" : "=l"(d) : "r"(u));
    return d;
}
__device__ __forceinline__ void unpack2(ull v, float& lo, float& hi) {
    unsigned int a, b;
    asm("mov.b64 {%0, %1}, %2;" : "=r"(a), "=r"(b) : "l"(v));
    lo = __uint_as_float(a); hi = __uint_as_float(b);
}

// Column swizzle: conflict-free LDS.64/STS for [c][128] layout.
__device__ __forceinline__ int swz(int col) {
    return col ^ (((col >> 5) & 3) << 1);
}

// ---------------------------------------------------------------------------
// Prep: index dtype detect + transpose x, W1, W2
// ---------------------------------------------------------------------------
__global__ void prep_kernel(const float* __restrict__ x,
                            const float* __restrict__ W1,
                            const float* __restrict__ W2,
                            const unsigned int* __restrict__ idx32)
{
    int tid = blockIdx.x * blockDim.x + threadIdx.x;

    if (tid == 0) {
        unsigned int orv = 0;
#pragma unroll 4
        for (int i = 0; i < 256; i++) orv |= idx32[2 * i + 1];
        g_idx_is64 = (orv == 0u) ? 1 : 0;
    }

    if (tid < NPTS) {
        int n = tid;
#pragma unroll
        for (int c4 = 0; c4 < CIN / 4; c4++) {
            float4 v;
            v.x = x[(c4 * 4 + 0) * NPTS + n];
            v.y = x[(c4 * 4 + 1) * NPTS + n];
            v.z = x[(c4 * 4 + 2) * NPTS + n];
            v.w = x[(c4 * 4 + 3) * NPTS + n];
            *(float4*)&g_xT[(size_t)n * CIN + c4 * 4] = v;
        }
    }
    if (tid < CH * HID) {
        int c = tid / HID, o = tid % HID;
        g_W1t[c * HID + o] = W1[o * CH + c];
    }
    if (tid < HID * OUTC) {
        int c = tid / OUTC, o = tid % OUTC;
        g_W2t[c * OUTC + o] = W2[o * HID + c];
    }
}

// ---------------------------------------------------------------------------
// Fused kernel. smem:
//   sh_h  [67][128]  (gathered features; later reused to stage W2 [64][128])
//   sh_h1 [64][128]  (hidden activations)
//   sh_w1 [67][64]
// Threads: 256 = ty(16: 4-row groups) x tx(16: m = tx&7, khalf = tx>>3).
// Column pairs: col = m*16 + khalf*8 + 2p (+e), p in [0,4).
// ---------------------------------------------------------------------------
#define OFF_H1  (CH * COLS)                 // 8576
#define OFF_W1  (OFF_H1 + HID * COLS)       // 16768
#define SMEM_FLOATS (OFF_W1 + CH * HID)     // 21056 -> 84224 B

extern __shared__ float smem[];

__global__ __launch_bounds__(256, 2)
void pointnet_kernel(const float* __restrict__ pos,
                     const float* __restrict__ sup,
                     const float* __restrict__ b1,
                     const float* __restrict__ b2,
                     const void* __restrict__ indices,
                     float* __restrict__ out)
{
    float* sh_h  = smem;
    float* sh_h1 = smem + OFF_H1;
    float* sh_w1 = smem + OFF_W1;
    float* sh_w2 = smem;                 // reuses sh_h after GEMM1

    const int tid = threadIdx.x;
    const int tx  = tid & 15;
    const int ty  = tid >> 4;
    const int m_base = blockIdx.x * TM;

    // ---- Stage W1 into smem ----
    for (int i = tid; i < CH * HID; i += 256)
        sh_w1[i] = g_W1t[i];

    // ---- Gather: 2 threads per column (split channel range) ----
    {
        int col   = tid & 127;
        int chalf = tid >> 7;
        int m = col >> 4, k = col & 15;
        long long lin = (long long)(m_base + m) * KNB + k;
        long long idxv;
        if (g_idx_is64) idxv = ((const long long*)indices)[lin];
        else            idxv = (long long)(((const int*)indices)[lin]);
        int ii = ((int)idxv) & (NPTS - 1);

        float* dst = sh_h + swz(col);
        const float4* xr = (const float4*)&g_xT[(size_t)ii * CIN];
        if (chalf == 0) {
#pragma unroll
            for (int q = 0; q < 8; q++) {
                float4 v = xr[q];
                dst[(4 * q + 0) * COLS] = v.x;
                dst[(4 * q + 1) * COLS] = v.y;
                dst[(4 * q + 2) * COLS] = v.z;
                dst[(4 * q + 3) * COLS] = v.w;
            }
        } else {
#pragma unroll
            for (int q = 8; q < 16; q++) {
                float4 v = xr[q];
                dst[(4 * q + 0) * COLS] = v.x;
                dst[(4 * q + 1) * COLS] = v.y;
                dst[(4 * q + 2) * COLS] = v.z;
                dst[(4 * q + 3) * COLS] = v.w;
            }
#pragma unroll
            for (int d = 0; d < 3; d++)
                dst[(CIN + d) * COLS] = pos[d * NPTS + ii] - sup[d * MPTS + m_base + m];
        }
    }
    __syncthreads();

    // Per-thread physical column offsets (pair-aligned, swizzled)
    const int m  = tx & 7;
    const int kh = tx >> 3;
    int pc[4];
#pragma unroll
    for (int p = 0; p < 4; p++) {
        int col = (m << 4) + (kh << 3) + (p << 1);
        pc[p] = swz(col);
    }

    // ---- GEMM1: rows ty*4..+4, f32x2 over column pairs ----
    ull acc[4][4];
    {
#pragma unroll
        for (int r = 0; r < 4; r++) {
            ull bb = dup2(__ldg(&b1[ty * 4 + r]));
#pragma unroll
            for (int p = 0; p < 4; p++) acc[r][p] = bb;
        }
#pragma unroll 4
        for (int c = 0; c < CH; c++) {
            float4 w = *(const float4*)&sh_w1[c * HID + ty * 4];
            ull w2[4];
            w2[0] = dup2(w.x); w2[1] = dup2(w.y);
            w2[2] = dup2(w.z); w2[3] = dup2(w.w);
            ull h2[4];
#pragma unroll
            for (int p = 0; p < 4; p++)
                h2[p] = *(const ull*)&sh_h[c * COLS + pc[p]];
#pragma unroll
            for (int r = 0; r < 4; r++)
#pragma unroll
                for (int p = 0; p < 4; p++)
                    acc[r][p] = fma2(w2[r], h2[p], acc[r][p]);
        }
    }
    __syncthreads();   // all GEMM1 reads of sh_h done

    // ---- Epilogue: relu -> sh_h1; stage W2 into (dead) sh_h region ----
#pragma unroll
    for (int r = 0; r < 4; r++)
#pragma unroll
        for (int p = 0; p < 4; p++) {
            float lo, hi;
            unpack2(acc[r][p], lo, hi);
            lo = fmaxf(lo, 0.0f); hi = fmaxf(hi, 0.0f);
            *(float2*)&sh_h1[(ty * 4 + r) * COLS + pc[p]] = make_float2(lo, hi);
        }
    {
        const float4* src = (const float4*)g_W2t;
        float4* dst4 = (float4*)sh_w2;
        for (int i = tid; i < (HID * OUTC) / 4; i += 256)
            dst4[i] = src[i];
    }
    __syncthreads();

    // ---- GEMM2 + max-pool ----
#pragma unroll 1
    for (int rh = 0; rh < 2; rh++) {
#pragma unroll
        for (int r = 0; r < 4; r++) {
            ull bb = dup2(__ldg(&b2[rh * 64 + ty * 4 + r]));
#pragma unroll
            for (int p = 0; p < 4; p++) acc[r][p] = bb;
        }
#pragma unroll 4
        for (int c = 0; c < HID; c++) {
            float4 w = *(const float4*)&sh_w2[c * OUTC + rh * 64 + ty * 4];
            ull w2[4];
            w2[0] = dup2(w.x); w2[1] = dup2(w.y);
            w2[2] = dup2(w.z); w2[3] = dup2(w.w);
            ull h2[4];
#pragma unroll
            for (int p = 0; p < 4; p++)
                h2[p] = *(const ull*)&sh_h1[c * COLS + pc[p]];
#pragma unroll
            for (int r = 0; r < 4; r++)
#pragma unroll
                for (int p = 0; p < 4; p++)
                    acc[r][p] = fma2(w2[r], h2[p], acc[r][p]);
        }
        // max over this thread's 8 k, then combine with partner (other khalf)
#pragma unroll
        for (int r = 0; r < 4; r++) {
            float mx;
            {
                float lo, hi;
                unpack2(acc[r][0], lo, hi);
                mx = fmaxf(lo, hi);
#pragma unroll
                for (int p = 1; p < 4; p++) {
                    unpack2(acc[r][p], lo, hi);
                    mx = fmaxf(mx, fmaxf(lo, hi));
                }
            }
            float other = __shfl_xor_sync(0xffffffffu, mx, 8);
            mx = fmaxf(mx, other);
            if (kh == 0) {
                int o = rh * 64 + ty * 4 + r;
                out[(size_t)o * MPTS + m_base + m] = mx;
            }
        }
    }
}

// ---------------------------------------------------------------------------
extern "C" void kernel_launch(void* const* d_in, const int* in_sizes, int n_in,
                              void* d_out, int out_size)
{
    const float *x = 0, *pos = 0, *sup = 0, *W1 = 0, *b1 = 0, *W2 = 0, *b2 = 0;
    const void* idx = 0;
    for (int i = 0; i < n_in; i++) {
        switch (in_sizes[i]) {
            case 4194304: x  = (const float*)d_in[i]; break;
            case 196608:  if (!pos) pos = (const float*)d_in[i];
                          else      sup = (const float*)d_in[i]; break;
            case 4288:    W1 = (const float*)d_in[i]; break;
            case 64:      b1 = (const float*)d_in[i]; break;
            case 8192:    W2 = (const float*)d_in[i]; break;
            case 128:     b2 = (const float*)d_in[i]; break;
            case 1048576: idx = d_in[i]; break;
            default: break;
        }
    }
    float* out = (float*)d_out;

    prep_kernel<<<(NPTS + 255) / 256, 256>>>(x, W1, W2, (const unsigned int*)idx);

    size_t smem_bytes = SMEM_FLOATS * sizeof(float);   // 84224 B
    cudaFuncSetAttribute(pointnet_kernel,
                         cudaFuncAttributeMaxDynamicSharedMemorySize,
                         (int)smem_bytes);
    pointnet_kernel<<<MPTS / TM, 256, smem_bytes>>>(pos, sup, b1, b2, idx, out);
}

// round 5
// speedup vs baseline: 4.3205x; 2.3951x over previous
#include <cuda_runtime.h>
#include <cuda_bf16.h>
#include <cstdint>

#define NPTS 65536
#define MPTS 65536
#define KNB  16
#define NTILES 4096          // MPTS*KNB / 256
#define GRID 148

// ---------------- device scratch ----------------
__device__ __align__(16) unsigned short g_xhi[(size_t)NPTS * 64];
__device__ __align__(16) unsigned short g_xlo[(size_t)NPTS * 64];
__device__ __align__(16) unsigned short g_w1hi[64 * 64];
__device__ __align__(16) unsigned short g_w1lo[64 * 64];
__device__ __align__(16) unsigned short g_w2hi[128 * 64];
__device__ __align__(16) unsigned short g_w2lo[128 * 64];
__device__ float g_w1pos[64 * 4];
__device__ int   g_idx_is64;

// ---------------- smem layout (bytes) ----------------
#define SM_W1HI 0
#define SM_W1LO (SM_W1HI + 64 * 144)          // 9216
#define SM_W2HI (SM_W1LO + 64 * 144)          // 18432
#define SM_W2LO (SM_W2HI + 128 * 144)         // 36864
#define SM_B1HI (SM_W2LO + 128 * 144)         // 55296
#define SM_B1LO (SM_B1HI + 256 * 144)         // 92160
#define SM_HHI  (SM_B1LO + 256 * 144)         // 129024
#define SM_HLO  (SM_HHI + 256 * 144)          // 165888
#define SM_PD   (SM_HLO + 256 * 144)          // 202752
#define SM_W1P  (SM_PD + 3 * 256 * 4)         // 205824
#define SM_POOL (SM_W1P + 64 * 16)            // 206848  (128 x 20 floats)
#define SM_TOTAL (SM_POOL + 128 * 20 * 4)     // 217088

// ---------------- helpers ----------------
__device__ __forceinline__ uint32_t smem_u32(const void* p) {
    uint32_t a;
    asm("{ .reg .u64 t; cvta.to.shared.u64 t, %1; cvt.u32.u64 %0, t; }" : "=r"(a) : "l"(p));
    return a;
}
__device__ __forceinline__ void ldsm4(uint32_t (&r)[4], uint32_t addr) {
    asm volatile("ldmatrix.sync.aligned.m8n8.x4.shared.b16 {%0,%1,%2,%3}, [%4];"
                 : "=r"(r[0]), "=r"(r[1]), "=r"(r[2]), "=r"(r[3]) : "r"(addr));
}
__device__ __forceinline__ void mma16816(float (&d)[4], const uint32_t (&a)[4],
                                         uint32_t b0, uint32_t b1) {
    asm volatile("mma.sync.aligned.m16n8k16.row.col.f32.bf16.bf16.f32 "
                 "{%0,%1,%2,%3}, {%4,%5,%6,%7}, {%8,%9}, {%0,%1,%2,%3};"
                 : "+f"(d[0]), "+f"(d[1]), "+f"(d[2]), "+f"(d[3])
                 : "r"(a[0]), "r"(a[1]), "r"(a[2]), "r"(a[3]), "r"(b0), "r"(b1));
}

// ---------------- prep: x -> bf16 hi/lo rows ----------------
__global__ __launch_bounds__(256) void prep_x_kernel(const float* __restrict__ x)
{
    __shared__ unsigned short shhi[128 * 72];
    __shared__ unsigned short shlo[128 * 72];
    const int p0 = blockIdx.x * 128;
    const int tid = threadIdx.x;

    for (int idx = tid; idx < 128 * 64; idx += 256) {
        int c = idx >> 7, p = idx & 127;
        float v = x[(size_t)c * NPTS + p0 + p];
        __nv_bfloat16 h = __float2bfloat16(v);
        __nv_bfloat16 l = __float2bfloat16(v - __bfloat162float(h));
        shhi[p * 72 + c] = *(unsigned short*)&h;
        shlo[p * 72 + c] = *(unsigned short*)&l;
    }
    __syncthreads();
    uint4* dh = (uint4*)(g_xhi + (size_t)p0 * 64);
    uint4* dl = (uint4*)(g_xlo + (size_t)p0 * 64);
    for (int i = tid; i < 1024; i += 256) {
        int p = i >> 3, q = i & 7;
        dh[i] = *(const uint4*)&shhi[p * 72 + q * 8];
        dl[i] = *(const uint4*)&shlo[p * 72 + q * 8];
    }
}

// ---------------- prep: weights ----------------
__global__ __launch_bounds__(256) void prep_w_kernel(const float* __restrict__ W1,
                                                     const float* __restrict__ W2,
                                                     const unsigned int* __restrict__ idx32)
{
    int tid = blockIdx.x * blockDim.x + threadIdx.x;
    if (tid == 0) {
        unsigned int orv = 0;
        for (int i = 0; i < 256; i++) orv |= idx32[2 * i + 1];
        g_idx_is64 = (orv == 0u) ? 1 : 0;
    }
    if (tid < 64 * 64) {
        int o = tid >> 6, k = tid & 63;
        float v = W1[o * 67 + k];
        __nv_bfloat16 h = __float2bfloat16(v);
        __nv_bfloat16 l = __float2bfloat16(v - __bfloat162float(h));
        g_w1hi[tid] = *(unsigned short*)&h;
        g_w1lo[tid] = *(unsigned short*)&l;
    }
    if (tid < 64) {
        g_w1pos[tid * 4 + 0] = W1[tid * 67 + 64];
        g_w1pos[tid * 4 + 1] = W1[tid * 67 + 65];
        g_w1pos[tid * 4 + 2] = W1[tid * 67 + 66];
        g_w1pos[tid * 4 + 3] = 0.0f;
    }
    if (tid < 128 * 64) {
        float v = W2[tid];
        __nv_bfloat16 h = __float2bfloat16(v);
        __nv_bfloat16 l = __float2bfloat16(v - __bfloat162float(h));
        g_w2hi[tid] = *(unsigned short*)&h;
        g_w2lo[tid] = *(unsigned short*)&l;
    }
}

// ---------------- main persistent kernel ----------------
extern __shared__ char smc[];

__global__ __launch_bounds__(512, 1)
void pointnet_mma_kernel(const float* __restrict__ pos,
                         const float* __restrict__ sup,
                         const float* __restrict__ b1,
                         const float* __restrict__ b2,
                         const void* __restrict__ indices,
                         float* __restrict__ out)
{
    const uint32_t sb = smem_u32(smc);
    const int tid = threadIdx.x;
    const int w = tid >> 5;
    const int l = tid & 31;
    const int is64 = g_idx_is64;

    // ---- stage weights once ----
    for (int i = tid; i < 1024; i += 512) {          // W1 hi/lo
        int buf = i >> 9, o = (i >> 3) & 63, c = i & 7;
        const uint4* s = (const uint4*)((buf ? g_w1lo : g_w1hi) + o * 64);
        *(uint4*)(smc + SM_W1HI + buf * 9216 + o * 144 + c * 16) = s[c];
    }
    for (int i = tid; i < 2048; i += 512) {          // W2 hi/lo
        int buf = i >> 10, o = (i >> 3) & 127, c = i & 7;
        const uint4* s = (const uint4*)((buf ? g_w2lo : g_w2hi) + o * 64);
        *(uint4*)(smc + SM_W2HI + buf * 18432 + o * 144 + c * 16) = s[c];
    }
    if (tid < 256) *(float*)(smc + SM_W1P + tid * 4) = g_w1pos[tid];
    __syncthreads();

    float* pdf   = (float*)(smc + SM_PD);
    float* poolf = (float*)(smc + SM_POOL);

    for (int tile = blockIdx.x; tile < NTILES; tile += gridDim.x) {
        // ================= gather =================
        {
            const int gg = l >> 3, cc = l & 7;
#pragma unroll
            for (int it = 0; it < 4; it++) {
                int p = it * 64 + w * 4 + gg;
                long long lin = (long long)tile * 256 + p;
                int ii;
                if (is64) ii = (int)((const long long*)indices)[lin] & (NPTS - 1);
                else      ii = ((const int*)indices)[lin] & (NPTS - 1);
                const uint4* sh = (const uint4*)(g_xhi + (size_t)ii * 64);
                const uint4* sl = (const uint4*)(g_xlo + (size_t)ii * 64);
                *(uint4*)(smc + SM_B1HI + p * 144 + cc * 16) = sh[cc];
                *(uint4*)(smc + SM_B1LO + p * 144 + cc * 16) = sl[cc];
            }
            if (tid < 256) {
                int p = tid;
                long long lin = (long long)tile * 256 + p;
                int ii;
                if (is64) ii = (int)((const long long*)indices)[lin] & (NPTS - 1);
                else      ii = ((const int*)indices)[lin] & (NPTS - 1);
                int m = tile * 16 + (p >> 4);
#pragma unroll
                for (int d = 0; d < 3; d++)
                    pdf[d * 256 + p] = pos[d * NPTS + ii] - sup[d * MPTS + m];
            }
        }
        __syncthreads();

        // ================= GEMM1: 64 x 256, K=64 =================
        {
            const int wm = w & 3, wn = w >> 2;
            const int o0 = wm * 16;
            float acc[8][4];
#pragma unroll
            for (int i = 0; i < 8; i++)
#pragma unroll
                for (int j = 0; j < 4; j++) acc[i][j] = 0.0f;

            const uint32_t arowH = sb + SM_W1HI +
                (o0 + ((l >> 3) & 1) * 8 + (l & 7)) * 144;
            const uint32_t arowL = arowH + 9216;
            const uint32_t browH = sb + SM_B1HI +
                (wn * 64 + ((l >> 4) & 1) * 8 + (l & 7)) * 144;
            const uint32_t browL = browH + 36864;

#pragma unroll
            for (int ks = 0; ks < 4; ks++) {
                uint32_t ach = (2 * ks + (l >> 4)) * 16;
                uint32_t bch = (2 * ks + ((l >> 3) & 1)) * 16;
                uint32_t ah[4], al[4];
                ldsm4(ah, arowH + ach);
                ldsm4(al, arowL + ach);
#pragma unroll
                for (int nbp = 0; nbp < 4; nbp++) {
                    uint32_t bh[4], bl[4];
                    ldsm4(bh, browH + nbp * (16 * 144) + bch);
                    mma16816(acc[2 * nbp],     ah, bh[0], bh[1]);
                    mma16816(acc[2 * nbp + 1], ah, bh[2], bh[3]);
                    mma16816(acc[2 * nbp],     al, bh[0], bh[1]);
                    mma16816(acc[2 * nbp + 1], al, bh[2], bh[3]);
                    ldsm4(bl, browL + nbp * (16 * 144) + bch);
                    mma16816(acc[2 * nbp],     ah, bl[0], bl[1]);
                    mma16816(acc[2 * nbp + 1], ah, bl[2], bl[3]);
                }
            }

            // ---- epilogue 1: pos-term + bias + relu -> H hi/lo ----
            const int o_lo = o0 + (l >> 2);
            const int o_hi = o_lo + 8;
            float4 wpl = *(const float4*)(smc + SM_W1P + o_lo * 16);
            float4 wph = *(const float4*)(smc + SM_W1P + o_hi * 16);
            float bl_ = __ldg(&b1[o_lo]);
            float bh_ = __ldg(&b1[o_hi]);
            const int paired = (((l >> 2) & 1) == 0);

#pragma unroll
            for (int nb = 0; nb < 8; nb++) {
                int cb = wn * 64 + nb * 8 + (l & 3) * 2;
                float2 q0 = *(const float2*)&pdf[0 * 256 + cb];
                float2 q1 = *(const float2*)&pdf[1 * 256 + cb];
                float2 q2 = *(const float2*)&pdf[2 * 256 + cb];
                float v[4];
                v[0] = fmaxf(acc[nb][0] + bl_ + wpl.x * q0.x + wpl.y * q1.x + wpl.z * q2.x, 0.0f);
                v[1] = fmaxf(acc[nb][1] + bl_ + wpl.x * q0.y + wpl.y * q1.y + wpl.z * q2.y, 0.0f);
                v[2] = fmaxf(acc[nb][2] + bh_ + wph.x * q0.x + wph.y * q1.x + wph.z * q2.x, 0.0f);
                v[3] = fmaxf(acc[nb][3] + bh_ + wph.x * q0.y + wph.y * q1.y + wph.z * q2.y, 0.0f);
                const int colv[4] = {cb, cb + 1, cb, cb + 1};
                const int ov[4]   = {o_lo, o_lo, o_hi, o_hi};
#pragma unroll
                for (int q = 0; q < 4; q++) {
                    __nv_bfloat16 hb = __float2bfloat16(v[q]);
                    float rem = v[q] - __bfloat162float(hb);
                    __nv_bfloat16 lb = __float2bfloat16(rem);
                    uint32_t uh = (uint32_t)(*(unsigned short*)&hb);
                    uint32_t ul = (uint32_t)(*(unsigned short*)&lb);
                    uint32_t ph = __shfl_xor_sync(0xffffffffu, uh, 4);
                    uint32_t pl = __shfl_xor_sync(0xffffffffu, ul, 4);
                    if (paired) {
                        uint32_t off = colv[q] * 144 + ov[q] * 2;
                        *(uint32_t*)(smc + SM_HHI + off) = uh | (ph << 16);
                        *(uint32_t*)(smc + SM_HLO + off) = ul | (pl << 16);
                    }
                }
            }
        }
        __syncthreads();

        // ================= GEMM2: 128 x 256, K=64 + max-pool =================
        {
            const int wm = w & 7, wn = w >> 3;
            const int o0 = wm * 16;
            float acc[16][4];
#pragma unroll
            for (int i = 0; i < 16; i++)
#pragma unroll
                for (int j = 0; j < 4; j++) acc[i][j] = 0.0f;

            const uint32_t arowH = sb + SM_W2HI +
                (o0 + ((l >> 3) & 1) * 8 + (l & 7)) * 144;
            const uint32_t arowL = arowH + 18432;
            const uint32_t browH = sb + SM_HHI +
                (wn * 128 + ((l >> 4) & 1) * 8 + (l & 7)) * 144;
            const uint32_t browL = browH + 36864;

#pragma unroll
            for (int ks = 0; ks < 4; ks++) {
                uint32_t ach = (2 * ks + (l >> 4)) * 16;
                uint32_t bch = (2 * ks + ((l >> 3) & 1)) * 16;
                uint32_t ah[4], al[4];
                ldsm4(ah, arowH + ach);
                ldsm4(al, arowL + ach);
#pragma unroll
                for (int nbp = 0; nbp < 8; nbp++) {
                    uint32_t bh[4], bl[4];
                    ldsm4(bh, browH + nbp * (16 * 144) + bch);
                    mma16816(acc[2 * nbp],     ah, bh[0], bh[1]);
                    mma16816(acc[2 * nbp + 1], ah, bh[2], bh[3]);
                    mma16816(acc[2 * nbp],     al, bh[0], bh[1]);
                    mma16816(acc[2 * nbp + 1], al, bh[2], bh[3]);
                    ldsm4(bl, browL + nbp * (16 * 144) + bch);
                    mma16816(acc[2 * nbp],     ah, bl[0], bl[1]);
                    mma16816(acc[2 * nbp + 1], ah, bl[2], bl[3]);
                }
            }

            // ---- pool over K=16 (2 nblocks + lane quad) ----
#pragma unroll
            for (int nbp = 0; nbp < 8; nbp++) {
                float mlo = fmaxf(fmaxf(acc[2 * nbp][0], acc[2 * nbp][1]),
                                  fmaxf(acc[2 * nbp + 1][0], acc[2 * nbp + 1][1]));
                float mhi = fmaxf(fmaxf(acc[2 * nbp][2], acc[2 * nbp][3]),
                                  fmaxf(acc[2 * nbp + 1][2], acc[2 * nbp + 1][3]));
                mlo = fmaxf(mlo, __shfl_xor_sync(0xffffffffu, mlo, 1));
                mlo = fmaxf(mlo, __shfl_xor_sync(0xffffffffu, mlo, 2));
                mhi = fmaxf(mhi, __shfl_xor_sync(0xffffffffu, mhi, 1));
                mhi = fmaxf(mhi, __shfl_xor_sync(0xffffffffu, mhi, 2));
                if ((l & 3) == 0) {
                    int mp = wn * 8 + nbp;
                    poolf[(o0 + (l >> 2)) * 20 + mp]     = mlo;
                    poolf[(o0 + 8 + (l >> 2)) * 20 + mp] = mhi;
                }
            }
        }
        __syncthreads();

        // ---- coalesced output: [o][m], +b2 ----
        {
            int o = tid >> 2, mg = tid & 3;
            float4 v = *(const float4*)(poolf + o * 20 + mg * 4);
            float bb = __ldg(&b2[o]);
            v.x += bb; v.y += bb; v.z += bb; v.w += bb;
            *(float4*)(out + (size_t)o * MPTS + tile * 16 + mg * 4) = v;
        }
        __syncthreads();
    }
}

// ---------------------------------------------------------------------------
extern "C" void kernel_launch(void* const* d_in, const int* in_sizes, int n_in,
                              void* d_out, int out_size)
{
    const float *x = 0, *pos = 0, *sup = 0, *W1 = 0, *b1 = 0, *W2 = 0, *b2 = 0;
    const void* idx = 0;
    for (int i = 0; i < n_in; i++) {
        switch (in_sizes[i]) {
            case 4194304: x  = (const float*)d_in[i]; break;
            case 196608:  if (!pos) pos = (const float*)d_in[i];
                          else      sup = (const float*)d_in[i]; break;
            case 4288:    W1 = (const float*)d_in[i]; break;
            case 64:      b1 = (const float*)d_in[i]; break;
            case 8192:    W2 = (const float*)d_in[i]; break;
            case 128:     b2 = (const float*)d_in[i]; break;
            case 1048576: idx = d_in[i]; break;
            default: break;
        }
    }
    float* out = (float*)d_out;

    prep_w_kernel<<<32, 256>>>(W1, W2, (const unsigned int*)idx);
    prep_x_kernel<<<NPTS / 128, 256>>>(x);

    cudaFuncSetAttribute(pointnet_mma_kernel,
                         cudaFuncAttributeMaxDynamicSharedMemorySize, SM_TOTAL);
    pointnet_mma_kernel<<<GRID, 512, SM_TOTAL>>>(pos, sup, b1, b2, idx, out);
}